// round 16
// baseline (speedup 1.0000x reference)
#include <cuda_runtime.h>
#include <cuda_bf16.h>
#include <math.h>
#include <stdint.h>

// ---------------- problem constants ----------------
#define BB 2048     // batch
#define TT 80       // time steps
#define EE 100      // embed dim
#define VV 10000    // vocab
#define UU 512      // hidden dim

#define NCTA 256    // persistent grid, 2 CTAs/SM (256 <= 148*2, single wave)
#define MT 128
#define NT 32

// H row layout: 1024 bytes = [0:512) level-0 int8, [512:1024) level-1 int8
#define HROW 1024

// smem per CTA: B resident 8 blocks x 4KB = 32KB, then 2 A stages x 32KB
#define SM_B    0
#define SM_A    32768
#define SM_TOT  (32768 + 2 * 32768)    // 98304 bytes -> 2 CTAs/SM (196KB < 227KB)

// quant constants: h = i1/127 + i2/16256 ; w = j1*s1 + j2*s1/128
#define C_A1 (1.f / 127.f)
#define C_A2 (1.f / 16256.f)

// ---------------- device scratch ----------------
__device__ __align__(16) uint8_t g_Hq[2][BB * HROW];   // 4 MB
__device__ __align__(16) float   g_P[VV * UU];         // 20 MB
__device__ __align__(16) int8_t  g_Wq[UU * HROW];      // 512 KB ([n][1024]: L0|L1)
__device__ __align__(16) int     g_xT[TT * BB];
__device__ unsigned int g_gbar[16][32];                // one counter per m-group, 128B apart
__device__ unsigned int g_wmax;

// ---------------- helpers ----------------
__device__ __forceinline__ uint32_t smem_u32(const void* p) {
    uint32_t a;
    asm("{ .reg .u64 t; cvta.to.shared.u64 t, %1; cvt.u32.u64 %0, t; }" : "=r"(a) : "l"(p));
    return a;
}
__device__ __forceinline__ uint32_t sw128(uint32_t off) { return off ^ ((off >> 3) & 0x70); }

#define CP_ASYNC16(sdst, gsrc) \
    asm volatile("cp.async.cg.shared.global [%0], [%1], 16;" :: "r"(sdst), "l"(gsrc) : "memory")
#define CP_COMMIT() asm volatile("cp.async.commit_group;" ::: "memory")
#define CP_WAIT0()  asm volatile("cp.async.wait_group 0;" ::: "memory")

// fast tanh: 1 - 2/(e^{2x}+1); inf-safe, ~ulp-level error
__device__ __forceinline__ float fast_tanh(float x) {
    float e = __expf(2.f * x);
    return 1.f - __fdividef(2.f, e + 1.f);
}

// m-group barrier wait (single counter, CG sync-with pattern) — R12-proven optimum
#define CWAIT(ctrp, tgt) do {                                                         \
    if (tid == 0) {                                                                   \
        unsigned int _v;                                                              \
        do {                                                                          \
            asm volatile("ld.acquire.gpu.global.u32 %0, [%1];"                        \
                         : "=r"(_v) : "l"(ctrp) : "memory");                          \
        } while ((int)(_v - (tgt)) < 0);                                              \
    }                                                                                 \
    __syncthreads();                                                                  \
} while (0)

// quantize h in (-1,1) to two int8 levels
__device__ __forceinline__ void hquant(float h, int& i1, int& i2) {
    i1 = __float2int_rn(h * 127.f);
    float r = h - (float)i1 * C_A1;
    i2 = __float2int_rn(r * 16256.f);
}

// ================= tiny setup kernels =================
__global__ void reset_kernel() {
    int i = threadIdx.x;
    if (i < 16) g_gbar[i][0] = 0;
    if (i == 16) g_wmax = 0;
}

__global__ __launch_bounds__(256) void wmax_kernel(const float* __restrict__ Wh) {
    int idx = blockIdx.x * 256 + threadIdx.x;
    float v = fabsf(Wh[idx]);
    #pragma unroll
    for (int o = 16; o; o >>= 1) v = fmaxf(v, __shfl_xor_sync(0xFFFFFFFFu, v, o));
    if ((threadIdx.x & 31) == 0) atomicMax(&g_wmax, __float_as_uint(v));
}

// fused: Wh quant (all 262144 ids) + x transpose (first 163840 ids)
__global__ __launch_bounds__(256) void wquant_xt_kernel(
    const float* __restrict__ Wh, const int* __restrict__ x)
{
    int idx = blockIdx.x * 256 + threadIdx.x;          // 0 .. UU*UU-1
    int n = idx >> 9, k = idx & 511;
    float wmax = __uint_as_float(g_wmax);
    float s1 = wmax * (1.f / 127.f);
    float w = Wh[k * UU + n];
    int j1 = __float2int_rn(__fdividef(w, s1));
    float r = w - (float)j1 * s1;
    int j2 = __float2int_rn(__fdividef(r * 128.f, s1));
    g_Wq[n * HROW + k]       = (int8_t)j1;
    g_Wq[n * HROW + 512 + k] = (int8_t)j2;
    if (idx < TT * BB) {
        int t = idx / BB, b = idx - t * BB;
        g_xT[idx] = x[b * TT + t];
    }
}

// P = emb @ Wx1 + b1  — v2: 128x128 CTA tile, 8x8 register micro-tiles
// (1 FMA/byte from smem -> FMA-rate bound instead of L1-bound)
__global__ __launch_bounds__(256) void p_kernel(
    const float* __restrict__ emb, const float* __restrict__ Wx,
    const float* __restrict__ b1)
{
    __shared__ float As[16][132];   // [k][m], padded
    __shared__ float Bs[16][132];   // [k][n], padded
    const int tid = threadIdx.x;
    const int tx = tid & 15;        // n-group: cols tx*8..+7
    const int ty = tid >> 4;        // m-group: rows ty*8..+7
    const int row0 = blockIdx.y * 128, col0 = blockIdx.x * 128;

    float acc[8][8] = {};

    for (int k0 = 0; k0 < 112; k0 += 16) {
        // load A tile: 128 m x 16 k (2 float4 per thread), transposed store
        #pragma unroll
        for (int i = 0; i < 2; i++) {
            int u = tid + i * 256;          // 0..511
            int m = u >> 2, lkq = u & 3;
            int ea = k0 + lkq * 4;
            int ar = row0 + m;
            float4 av = (ea < EE && ar < VV) ? *(const float4*)&emb[ar * EE + ea]
                                             : make_float4(0.f, 0.f, 0.f, 0.f);
            __syncthreads();                // (only first i matters; harmless 2nd)
            As[lkq * 4 + 0][m] = av.x; As[lkq * 4 + 1][m] = av.y;
            As[lkq * 4 + 2][m] = av.z; As[lkq * 4 + 3][m] = av.w;
        }
        // load B tile: 16 k x 128 n (2 float4 per thread)
        #pragma unroll
        for (int i = 0; i < 2; i++) {
            int u = tid + i * 256;          // 0..511
            int lk = u >> 5, lnq = u & 31;
            int eb = k0 + lk;
            float4 bv = (eb < EE) ? *(const float4*)&Wx[eb * UU + col0 + lnq * 4]
                                  : make_float4(0.f, 0.f, 0.f, 0.f);
            *(float4*)&Bs[lk][lnq * 4] = bv;
        }
        __syncthreads();
        #pragma unroll
        for (int k = 0; k < 16; k++) {
            float ar8[8], br8[8];
            *(float4*)&ar8[0] = *(const float4*)&As[k][ty * 8];
            *(float4*)&ar8[4] = *(const float4*)&As[k][ty * 8 + 4];
            *(float4*)&br8[0] = *(const float4*)&Bs[k][tx * 8];
            *(float4*)&br8[4] = *(const float4*)&Bs[k][tx * 8 + 4];
            #pragma unroll
            for (int i = 0; i < 8; i++)
                #pragma unroll
                for (int j = 0; j < 8; j++)
                    acc[i][j] += ar8[i] * br8[j];
        }
        __syncthreads();
    }
    #pragma unroll
    for (int i = 0; i < 8; i++) {
        int r = row0 + ty * 8 + i;
        if (r < VV) {
            #pragma unroll
            for (int j = 0; j < 8; j += 4) {
                int c = col0 + tx * 8 + j;
                float4 v;
                v.x = acc[i][j + 0] + b1[c + 0];
                v.y = acc[i][j + 1] + b1[c + 1];
                v.z = acc[i][j + 2] + b1[c + 2];
                v.w = acc[i][j + 3] + b1[c + 3];
                *(float4*)&g_P[r * UU + c] = v;
            }
        }
    }
}

// ================= persistent RNN kernel (IMMA s8, 2 CTA/SM) =================
// warp tile: m32 x n16. B blocks: (lvl*4 + c) * 4KB. A stage: 32KB (L0|L1 16KB each).
__device__ __forceinline__ void compute_stage_s8(
    uint32_t aT, uint32_t bB, int c, int warp_m, int warp_n, int lane,
    int acc1[2][2][4], int acc2[2][2][4])
{
    const int g = lane >> 3;
    #pragma unroll
    for (int kf = 0; kf < 4; kf++) {           // 4 k-steps of 32 int8
        uint32_t a_[2][2][4];
        #pragma unroll
        for (int mi = 0; mi < 2; mi++) {
            uint32_t off = sw128((warp_m * 32 + mi * 16 + (g & 1) * 8 + (lane & 7)) * 128
                                 + kf * 32 + (g >> 1) * 16);
            #pragma unroll
            for (int lvl = 0; lvl < 2; lvl++) {
                asm volatile("ldmatrix.sync.aligned.m8n8.x4.shared.b16 {%0,%1,%2,%3}, [%4];"
                    : "=r"(a_[mi][lvl][0]), "=r"(a_[mi][lvl][1]),
                      "=r"(a_[mi][lvl][2]), "=r"(a_[mi][lvl][3])
                    : "r"(aT + lvl * 16384 + off));
            }
        }
        uint32_t b_[2][2][2];       // [lvl][ni][2]
        {
            uint32_t off = sw128((warp_n * 16 + (g >> 1) * 8 + (lane & 7)) * 128
                                 + kf * 32 + (g & 1) * 16);
            #pragma unroll
            for (int lvl = 0; lvl < 2; lvl++) {
                asm volatile("ldmatrix.sync.aligned.m8n8.x4.shared.b16 {%0,%1,%2,%3}, [%4];"
                    : "=r"(b_[lvl][0][0]), "=r"(b_[lvl][0][1]),
                      "=r"(b_[lvl][1][0]), "=r"(b_[lvl][1][1])
                    : "r"(bB + (lvl * 4 + c) * 4096 + off));
            }
        }
        #pragma unroll
        for (int mi = 0; mi < 2; mi++)
            #pragma unroll
            for (int ni = 0; ni < 2; ni++) {
                #define IMMA(ACC, AL, BL)                                             \
                    asm volatile(                                                     \
                        "mma.sync.aligned.m16n8k32.row.col.s32.s8.s8.s32 "            \
                        "{%0,%1,%2,%3}, {%4,%5,%6,%7}, {%8,%9}, {%0,%1,%2,%3};"       \
                        : "+r"(ACC[mi][ni][0]), "+r"(ACC[mi][ni][1]),                 \
                          "+r"(ACC[mi][ni][2]), "+r"(ACC[mi][ni][3])                  \
                        : "r"(a_[mi][AL][0]), "r"(a_[mi][AL][1]),                     \
                          "r"(a_[mi][AL][2]), "r"(a_[mi][AL][3]),                     \
                          "r"(b_[BL][ni][0]), "r"(b_[BL][ni][1]))
                IMMA(acc1, 0, 0);   // i1*j1
                IMMA(acc2, 1, 0);   // i2*j1
                IMMA(acc2, 0, 1);   // i1*j2
                #undef IMMA
            }
    }
}

__global__ __launch_bounds__(256, 2) void rnn_kernel(
    const float* __restrict__ Wout, const float* __restrict__ bout,
    float* __restrict__ out)
{
    extern __shared__ char smem[];
    const uint32_t bB = smem_u32(smem) + SM_B;
    const uint32_t aB = smem_u32(smem) + SM_A;

    const int tid  = threadIdx.x;
    const int wid  = tid >> 5;
    const int lane = tid & 31;
    const int warp_m = wid >> 1;           // 0..3 : m32 band
    const int warp_n = wid & 1;            // 0..1 : n16 band
    const int n_tile = blockIdx.x & 15;
    const int m_tile = blockIdx.x >> 4;
    const int N0 = n_tile * NT;
    const int M0 = m_tile * MT;
    unsigned int* const my_bar = &g_gbar[m_tile][0];

    const float wmax = __uint_as_float(g_wmax);
    const float f1 = wmax * (1.f / 16129.f);       // (1/127)*(wmax/127)
    const float f2 = f1 * (1.f / 128.f);

    // ---- load resident B slice once: 8 blocks (lvl*4 + c) x 4KB ----
    #pragma unroll 4
    for (int i = 0; i < 8; i++) {
        int u = tid + i * 256;           // 2048 16B units
        int blk = u >> 8, rm = u & 255;
        int n = rm >> 3, kg = rm & 7;
        int koff = (blk >> 2) * 512 + (blk & 3) * 128 + kg * 16;
        CP_ASYNC16(bB + blk * 4096 + sw128(n * 128 + kg * 16),
                   g_Wq + (size_t)(N0 + n) * HROW + koff);
    }
    CP_COMMIT(); CP_WAIT0();
    __syncthreads();

    #define ISSUE_A(c) do {                                                           \
        _Pragma("unroll")                                                             \
        for (int i = 0; i < 4; i++) {                                                 \
            int u = tid + i * 256; int m = u >> 3; int kg = u & 7;                    \
            uint32_t sd = aB + ((c) & 1) * 32768 + sw128(m * 128 + kg * 16);          \
            const uint8_t* gs = Hsrc + (size_t)(M0 + m) * HROW + (c) * 128 + kg * 16; \
            CP_ASYNC16(sd, gs);                                                       \
            CP_ASYNC16(sd + 16384, gs + 512);                                         \
        }                                                                             \
        CP_COMMIT();                                                                  \
    } while (0)

    const int r = lane >> 2, q = lane & 3;
    const int gmA_base = M0 + warp_m * 32 + r;

    for (int t = 0; t < TT; t++) {
        const int src = t & 1, dst = src ^ 1;
        int acc1[2][2][4] = {};
        int acc2[2][2][4] = {};

        const int* __restrict__ xrow = g_xT + t * BB;
        const int tokA0 = xrow[gmA_base];
        const int tokB0 = xrow[gmA_base + 8];
        const int tokA1 = xrow[gmA_base + 16];
        const int tokB1 = xrow[gmA_base + 24];

        if (t > 0) {
            const uint8_t* __restrict__ Hsrc = g_Hq[src];
            CWAIT(my_bar, 16u * (unsigned)t);      // all 16 producers of my rows done
            ISSUE_A(0);
            #pragma unroll
            for (int kb = 0; kb < 4; kb++) {
                CP_WAIT0();          // my copies of chunk kb complete
                __syncthreads();     // publish everyone's chunk-kb copies
                if (kb < 3) ISSUE_A(kb + 1);   // overlaps compute(kb)
                compute_stage_s8(aB + (kb & 1) * 32768, bB, kb,
                                 warp_m, warp_n, lane, acc1, acc2);
            }
        }

        // ---- epilogue: h = tanh(f1*acc1 + f2*acc2 + P[tok]); quantize 2-level ----
        {
            uint8_t* __restrict__ hbase = g_Hq[dst];
            const int toks[2][2] = {{tokA0, tokB0}, {tokA1, tokB1}};
            #pragma unroll
            for (int mi = 0; mi < 2; mi++) {
                const int gmA = gmA_base + mi * 16;
                const int gmB = gmA + 8;
                const float* __restrict__ pA = g_P + (size_t)toks[mi][0] * UU;
                const float* __restrict__ pB = g_P + (size_t)toks[mi][1] * UU;
                uint8_t* __restrict__ dA = hbase + (size_t)gmA * HROW;
                uint8_t* __restrict__ dB = hbase + (size_t)gmB * HROW;
                #pragma unroll
                for (int ni = 0; ni < 2; ni++) {
                    const int gc = N0 + warp_n * 16 + ni * 8 + q * 2;
                    float2 pa = *(const float2*)(pA + gc);
                    float2 pb = *(const float2*)(pB + gc);
                    float h0 = fast_tanh((float)acc1[mi][ni][0] * f1 + (float)acc2[mi][ni][0] * f2 + pa.x);
                    float h1 = fast_tanh((float)acc1[mi][ni][1] * f1 + (float)acc2[mi][ni][1] * f2 + pa.y);
                    float h2 = fast_tanh((float)acc1[mi][ni][2] * f1 + (float)acc2[mi][ni][2] * f2 + pb.x);
                    float h3 = fast_tanh((float)acc1[mi][ni][3] * f1 + (float)acc2[mi][ni][3] * f2 + pb.y);
                    int a1i, a2i, b1i, b2i, c1i, c2i, d1i, d2i;
                    hquant(h0, a1i, a2i); hquant(h1, b1i, b2i);
                    hquant(h2, c1i, c2i); hquant(h3, d1i, d2i);
                    *(unsigned short*)(dA + gc) =
                        (unsigned short)((a1i & 0xFF) | ((b1i & 0xFF) << 8));
                    *(unsigned short*)(dA + 512 + gc) =
                        (unsigned short)((a2i & 0xFF) | ((b2i & 0xFF) << 8));
                    *(unsigned short*)(dB + gc) =
                        (unsigned short)((c1i & 0xFF) | ((d1i & 0xFF) << 8));
                    *(unsigned short*)(dB + 512 + gc) =
                        (unsigned short)((c2i & 0xFF) | ((d2i & 0xFF) << 8));
                }
            }
        }

        // arrive on my m-group counter (stores -> cta sync -> release)
        __syncthreads();
        if (tid == 0)
            asm volatile("red.release.gpu.global.add.u32 [%0], 1;" :: "l"(my_bar) : "memory");
    }
    #undef ISSUE_A

    // ---- output phase: rows M0..M0+127, by the 16 CTAs with n_tile==0 ----
    if (n_tile == 0) {
        CWAIT(my_bar, 16u * TT);
        const uint8_t* __restrict__ hb = g_Hq[0];
        const float bo = bout[0];
        #pragma unroll 4
        for (int rr = 0; rr < 16; rr++) {
            const int gm = M0 + wid * 16 + rr;
            const uint8_t* row = hb + (size_t)gm * HROW;
            float s = 0.f;
            #pragma unroll
            for (int k = lane; k < UU; k += 32) {
                float hv = (float)((int8_t)row[k]) * C_A1
                         + (float)((int8_t)row[512 + k]) * C_A2;
                s += hv * Wout[k];
            }
            #pragma unroll
            for (int o = 16; o; o >>= 1) s += __shfl_xor_sync(0xFFFFFFFFu, s, o);
            if (lane == 0) out[gm] = 1.f / (1.f + expf(-(s + bo)));
        }
    }
}

// ================= launcher =================
extern "C" void kernel_launch(void* const* d_in, const int* in_sizes, int n_in,
                              void* d_out, int out_size)
{
    (void)in_sizes; (void)n_in; (void)out_size;
    const int*   x    = (const int*)  d_in[0];
    const float* emb  = (const float*)d_in[1];
    // Wx0/Wh0/b0 (d_in[2..4]) are dead code in the reference.
    const float* Wx1  = (const float*)d_in[5];
    const float* Wh1  = (const float*)d_in[6];
    const float* b1   = (const float*)d_in[7];
    const float* Wout = (const float*)d_in[8];
    const float* bout = (const float*)d_in[9];
    float* out = (float*)d_out;

    cudaFuncSetAttribute(rnn_kernel, cudaFuncAttributeMaxDynamicSharedMemorySize, SM_TOT);

    reset_kernel<<<1, 32>>>();
    wmax_kernel<<<UU * UU / 256, 256>>>(Wh1);
    wquant_xt_kernel<<<UU * UU / 256, 256>>>(Wh1, x);
    p_kernel<<<dim3(4, 79), 256>>>(emb, Wx1, b1);
    rnn_kernel<<<NCTA, 256, SM_TOT>>>(Wout, bout, out);
}

// round 17
// speedup vs baseline: 1.0501x; 1.0501x over previous
#include <cuda_runtime.h>
#include <cuda_bf16.h>
#include <math.h>
#include <stdint.h>

// ---------------- problem constants ----------------
#define BB 2048     // batch
#define TT 80       // time steps
#define EE 100      // embed dim
#define VV 10000    // vocab
#define UU 512      // hidden dim
#define VPAD 10112  // 79 * 128 (M-tile padded vocab)

#define NCTA 256    // persistent grid, 2 CTAs/SM (256 <= 148*2, single wave)
#define MT 128
#define NT 32

// H row layout: 1024 bytes = [0:512) level-0 int8, [512:1024) level-1 int8
#define HROW 1024

// rnn smem: B resident 8 blocks x 4KB = 32KB, then 2 A stages x 32KB
#define SM_B    0
#define SM_A    32768
#define SM_TOT  (32768 + 2 * 32768)    // 98304 -> 2 CTAs/SM

// p_imma smem: B blocks 0..4 (20KB incl. lvl-1 block at 16384) + A 32KB
#define PSM_A    20480
#define PSM_TOT  (20480 + 32768)       // 53248

// quant constants: h = i1/127 + i2/16256 ; w = j1*s1 + j2*s1/128
#define C_A1 (1.f / 127.f)
#define C_A2 (1.f / 16256.f)

// ---------------- device scratch ----------------
__device__ __align__(16) uint8_t g_Hq[2][BB * HROW];     // 4 MB
__device__ __align__(16) float   g_P[VV * UU];           // 20 MB
__device__ __align__(16) int8_t  g_Wq[UU * HROW];        // 512 KB ([n][1024]: L0|L1)
__device__ __align__(16) int8_t  g_Eq[VPAD * 256];       // emb quant [row][256]: L0|L1 (padded rows stay 0)
__device__ __align__(16) int8_t  g_Wxq[UU * 256];        // WxT quant [n][256]: L0|L1
__device__ __align__(16) int     g_xT[TT * BB];
__device__ unsigned int g_gbar[16][32];                  // one counter per m-group, 128B apart
__device__ unsigned int g_wmax, g_emax, g_wxmax;

// ---------------- helpers ----------------
__device__ __forceinline__ uint32_t smem_u32(const void* p) {
    uint32_t a;
    asm("{ .reg .u64 t; cvta.to.shared.u64 t, %1; cvt.u32.u64 %0, t; }" : "=r"(a) : "l"(p));
    return a;
}
__device__ __forceinline__ uint32_t sw128(uint32_t off) { return off ^ ((off >> 3) & 0x70); }

#define CP_ASYNC16(sdst, gsrc) \
    asm volatile("cp.async.cg.shared.global [%0], [%1], 16;" :: "r"(sdst), "l"(gsrc) : "memory")
#define CP_COMMIT() asm volatile("cp.async.commit_group;" ::: "memory")
#define CP_WAIT0()  asm volatile("cp.async.wait_group 0;" ::: "memory")

// fast tanh: 1 - 2/(e^{2x}+1); inf-safe, ~ulp-level error
__device__ __forceinline__ float fast_tanh(float x) {
    float e = __expf(2.f * x);
    return 1.f - __fdividef(2.f, e + 1.f);
}

// m-group barrier wait (single counter, CG sync-with pattern) — R12-proven optimum
#define CWAIT(ctrp, tgt) do {                                                         \
    if (tid == 0) {                                                                   \
        unsigned int _v;                                                              \
        do {                                                                          \
            asm volatile("ld.acquire.gpu.global.u32 %0, [%1];"                        \
                         : "=r"(_v) : "l"(ctrp) : "memory");                          \
        } while ((int)(_v - (tgt)) < 0);                                              \
    }                                                                                 \
    __syncthreads();                                                                  \
} while (0)

// quantize h in (-1,1) to two int8 levels
__device__ __forceinline__ void hquant(float h, int& i1, int& i2) {
    i1 = __float2int_rn(h * 127.f);
    float r = h - (float)i1 * C_A1;
    i2 = __float2int_rn(r * 16256.f);
}

// generic 2-level quant with scale s1 = vmax/127 (inv1 = 127/vmax)
__device__ __forceinline__ void q2(float v, float s1, float inv1, int8_t& j1, int8_t& j2) {
    int a = __float2int_rn(v * inv1);
    float r = v - (float)a * s1;
    int b = __float2int_rn(r * inv1 * 128.f);
    j1 = (int8_t)a; j2 = (int8_t)b;
}

// ================= setup kernels =================
__global__ void reset_kernel() {
    int i = threadIdx.x;
    if (i < 16) g_gbar[i][0] = 0;
    if (i == 16) g_wmax = 0;
    if (i == 17) g_emax = 0;
    if (i == 18) g_wxmax = 0;
}

// fused abs-max of emb (1e6), Wh (262144), Wx (51200); 4 elems/thread
__global__ __launch_bounds__(256) void max_kernel(
    const float* __restrict__ emb, const float* __restrict__ Wh,
    const float* __restrict__ Wx)
{
    int gid = blockIdx.x * 256 + threadIdx.x;
    float me = 0.f, mh = 0.f, mx = 0.f;
    #pragma unroll
    for (int j = 0; j < 4; j++) {
        int i = gid * 4 + j;
        if (i < VV * EE) me = fmaxf(me, fabsf(emb[i]));
        if (i < UU * UU) mh = fmaxf(mh, fabsf(Wh[i]));
        if (i < EE * UU) mx = fmaxf(mx, fabsf(Wx[i]));
    }
    #pragma unroll
    for (int o = 16; o; o >>= 1) {
        me = fmaxf(me, __shfl_xor_sync(0xFFFFFFFFu, me, o));
        mh = fmaxf(mh, __shfl_xor_sync(0xFFFFFFFFu, mh, o));
        mx = fmaxf(mx, __shfl_xor_sync(0xFFFFFFFFu, mx, o));
    }
    if ((threadIdx.x & 31) == 0) {
        if (me > 0.f) atomicMax(&g_emax, __float_as_uint(me));
        if (mh > 0.f) atomicMax(&g_wmax, __float_as_uint(mh));
        if (mx > 0.f) atomicMax(&g_wxmax, __float_as_uint(mx));
    }
}

// fused quant: emb (VV*128 slots), Wh (UU*UU), WxT (UU*128), x transpose
__global__ __launch_bounds__(256) void quant_kernel(
    const float* __restrict__ emb, const float* __restrict__ Wh,
    const float* __restrict__ Wx, const int* __restrict__ x)
{
    int idx = blockIdx.x * 256 + threadIdx.x;          // 0 .. VV*128-1 (1.28M)
    // --- emb: row = idx>>7, k = idx&127 ---
    {
        int row = idx >> 7, k = idx & 127;
        float em = __uint_as_float(g_emax);
        float s1 = em * (1.f / 127.f), inv1 = __fdividef(127.f, em);
        float e = (k < EE) ? emb[row * EE + k] : 0.f;
        int8_t a, b; q2(e, s1, inv1, a, b);
        g_Eq[row * 256 + k]       = a;
        g_Eq[row * 256 + 128 + k] = b;
    }
    // --- Wh: [k][n] -> g_Wq[n][k]/[n][512+k] ---
    if (idx < UU * UU) {
        int n = idx >> 9, k = idx & 511;
        float wm = __uint_as_float(g_wmax);
        float s1 = wm * (1.f / 127.f), inv1 = __fdividef(127.f, wm);
        int8_t a, b; q2(Wh[k * UU + n], s1, inv1, a, b);
        g_Wq[n * HROW + k]       = a;
        g_Wq[n * HROW + 512 + k] = b;
    }
    // --- Wx: [k][n] -> g_Wxq[n][256]: L0|L1, k padded to 128 ---
    if (idx < UU * 128) {
        int n = idx >> 7, k = idx & 127;
        float xm = __uint_as_float(g_wxmax);
        float s1 = xm * (1.f / 127.f), inv1 = __fdividef(127.f, xm);
        float v = (k < EE) ? Wx[k * UU + n] : 0.f;
        int8_t a, b; q2(v, s1, inv1, a, b);
        g_Wxq[n * 256 + k]       = a;
        g_Wxq[n * 256 + 128 + k] = b;
    }
    // --- x transpose ---
    if (idx < TT * BB) {
        int t = idx / BB, b = idx - t * BB;
        g_xT[idx] = x[b * TT + t];
    }
}

// ================= shared IMMA stage (proven since R9) =================
// warp tile: m32 x n16. B blocks: (lvl*4 + c) * 4KB. A: aT + lvl*16384.
__device__ __forceinline__ void compute_stage_s8(
    uint32_t aT, uint32_t bB, int c, int warp_m, int warp_n, int lane,
    int acc1[2][2][4], int acc2[2][2][4])
{
    const int g = lane >> 3;
    #pragma unroll
    for (int kf = 0; kf < 4; kf++) {           // 4 k-steps of 32 int8
        uint32_t a_[2][2][4];
        #pragma unroll
        for (int mi = 0; mi < 2; mi++) {
            uint32_t off = sw128((warp_m * 32 + mi * 16 + (g & 1) * 8 + (lane & 7)) * 128
                                 + kf * 32 + (g >> 1) * 16);
            #pragma unroll
            for (int lvl = 0; lvl < 2; lvl++) {
                asm volatile("ldmatrix.sync.aligned.m8n8.x4.shared.b16 {%0,%1,%2,%3}, [%4];"
                    : "=r"(a_[mi][lvl][0]), "=r"(a_[mi][lvl][1]),
                      "=r"(a_[mi][lvl][2]), "=r"(a_[mi][lvl][3])
                    : "r"(aT + lvl * 16384 + off));
            }
        }
        uint32_t b_[2][2][2];       // [lvl][ni][2]
        {
            uint32_t off = sw128((warp_n * 16 + (g >> 1) * 8 + (lane & 7)) * 128
                                 + kf * 32 + (g & 1) * 16);
            #pragma unroll
            for (int lvl = 0; lvl < 2; lvl++) {
                asm volatile("ldmatrix.sync.aligned.m8n8.x4.shared.b16 {%0,%1,%2,%3}, [%4];"
                    : "=r"(b_[lvl][0][0]), "=r"(b_[lvl][0][1]),
                      "=r"(b_[lvl][1][0]), "=r"(b_[lvl][1][1])
                    : "r"(bB + (lvl * 4 + c) * 4096 + off));
            }
        }
        #pragma unroll
        for (int mi = 0; mi < 2; mi++)
            #pragma unroll
            for (int ni = 0; ni < 2; ni++) {
                #define IMMA(ACC, AL, BL)                                             \
                    asm volatile(                                                     \
                        "mma.sync.aligned.m16n8k32.row.col.s32.s8.s8.s32 "            \
                        "{%0,%1,%2,%3}, {%4,%5,%6,%7}, {%8,%9}, {%0,%1,%2,%3};"       \
                        : "+r"(ACC[mi][ni][0]), "+r"(ACC[mi][ni][1]),                 \
                          "+r"(ACC[mi][ni][2]), "+r"(ACC[mi][ni][3])                  \
                        : "r"(a_[mi][AL][0]), "r"(a_[mi][AL][1]),                     \
                          "r"(a_[mi][AL][2]), "r"(a_[mi][AL][3]),                     \
                          "r"(b_[BL][ni][0]), "r"(b_[BL][ni][1]))
                IMMA(acc1, 0, 0);   // i1*j1
                IMMA(acc2, 1, 0);   // i2*j1
                IMMA(acc2, 0, 1);   // i1*j2
                #undef IMMA
            }
    }
}

// ================= P = emb @ Wx1 + b1 via IMMA =================
__global__ __launch_bounds__(256) void p_imma_kernel(const float* __restrict__ b1)
{
    extern __shared__ char smem[];
    const uint32_t bB = smem_u32(smem);
    const uint32_t aB = smem_u32(smem) + PSM_A;

    const int tid  = threadIdx.x;
    const int wid  = tid >> 5;
    const int lane = tid & 31;
    const int warp_m = wid >> 1, warp_n = wid & 1;
    const int N0 = blockIdx.x * NT;        // 0..480
    const int M0 = blockIdx.y * MT;        // 0..9984

    // B slice: 32 n x 128 k, 2 levels -> blocks 0 (L0) and 4 (L1)
    #pragma unroll
    for (int i = 0; i < 2; i++) {
        int u = tid + i * 256;             // 512 16B units
        int lvl = u >> 8, rm = u & 255;
        int n = rm >> 3, kg = rm & 7;
        CP_ASYNC16(bB + (lvl * 4) * 4096 + sw128(n * 128 + kg * 16),
                   g_Wxq + (size_t)(N0 + n) * 256 + lvl * 128 + kg * 16);
    }
    // A: 128 rows x 128 k, 2 levels
    #pragma unroll
    for (int i = 0; i < 4; i++) {
        int u = tid + i * 256;             // 1024 16B units
        int m = u >> 3, kg = u & 7;
        const int8_t* gs = g_Eq + (size_t)(M0 + m) * 256 + kg * 16;
        uint32_t sd = aB + sw128(m * 128 + kg * 16);
        CP_ASYNC16(sd, gs);
        CP_ASYNC16(sd + 16384, gs + 128);
    }
    CP_COMMIT(); CP_WAIT0();
    __syncthreads();

    int acc1[2][2][4] = {};
    int acc2[2][2][4] = {};
    compute_stage_s8(aB, bB, 0, warp_m, warp_n, lane, acc1, acc2);

    const float em = __uint_as_float(g_emax);
    const float xm = __uint_as_float(g_wxmax);
    const float f1 = em * xm * (1.f / 16129.f);
    const float f2 = f1 * (1.f / 128.f);

    const int r = lane >> 2, q = lane & 3;
    #pragma unroll
    for (int mi = 0; mi < 2; mi++) {
        const int gmA = M0 + warp_m * 32 + mi * 16 + r;
        const int gmB = gmA + 8;
        #pragma unroll
        for (int ni = 0; ni < 2; ni++) {
            const int gc = N0 + warp_n * 16 + ni * 8 + q * 2;
            float bv0 = b1[gc], bv1 = b1[gc + 1];
            if (gmA < VV) {
                g_P[(size_t)gmA * UU + gc]     = (float)acc1[mi][ni][0] * f1 + (float)acc2[mi][ni][0] * f2 + bv0;
                g_P[(size_t)gmA * UU + gc + 1] = (float)acc1[mi][ni][1] * f1 + (float)acc2[mi][ni][1] * f2 + bv1;
            }
            if (gmB < VV) {
                g_P[(size_t)gmB * UU + gc]     = (float)acc1[mi][ni][2] * f1 + (float)acc2[mi][ni][2] * f2 + bv0;
                g_P[(size_t)gmB * UU + gc + 1] = (float)acc1[mi][ni][3] * f1 + (float)acc2[mi][ni][3] * f2 + bv1;
            }
        }
    }
}

// ================= persistent RNN kernel (IMMA s8, 2 CTA/SM) — unchanged R15 =================
__global__ __launch_bounds__(256, 2) void rnn_kernel(
    const float* __restrict__ Wout, const float* __restrict__ bout,
    float* __restrict__ out)
{
    extern __shared__ char smem[];
    const uint32_t bB = smem_u32(smem) + SM_B;
    const uint32_t aB = smem_u32(smem) + SM_A;

    const int tid  = threadIdx.x;
    const int wid  = tid >> 5;
    const int lane = tid & 31;
    const int warp_m = wid >> 1;
    const int warp_n = wid & 1;
    const int n_tile = blockIdx.x & 15;
    const int m_tile = blockIdx.x >> 4;
    const int N0 = n_tile * NT;
    const int M0 = m_tile * MT;
    unsigned int* const my_bar = &g_gbar[m_tile][0];

    const float wmax = __uint_as_float(g_wmax);
    const float f1 = wmax * (1.f / 16129.f);
    const float f2 = f1 * (1.f / 128.f);

    #pragma unroll 4
    for (int i = 0; i < 8; i++) {
        int u = tid + i * 256;
        int blk = u >> 8, rm = u & 255;
        int n = rm >> 3, kg = rm & 7;
        int koff = (blk >> 2) * 512 + (blk & 3) * 128 + kg * 16;
        CP_ASYNC16(bB + blk * 4096 + sw128(n * 128 + kg * 16),
                   g_Wq + (size_t)(N0 + n) * HROW + koff);
    }
    CP_COMMIT(); CP_WAIT0();
    __syncthreads();

    #define ISSUE_A(c) do {                                                           \
        _Pragma("unroll")                                                             \
        for (int i = 0; i < 4; i++) {                                                 \
            int u = tid + i * 256; int m = u >> 3; int kg = u & 7;                    \
            uint32_t sd = aB + ((c) & 1) * 32768 + sw128(m * 128 + kg * 16);          \
            const uint8_t* gs = Hsrc + (size_t)(M0 + m) * HROW + (c) * 128 + kg * 16; \
            CP_ASYNC16(sd, gs);                                                       \
            CP_ASYNC16(sd + 16384, gs + 512);                                         \
        }                                                                             \
        CP_COMMIT();                                                                  \
    } while (0)

    const int r = lane >> 2, q = lane & 3;
    const int gmA_base = M0 + warp_m * 32 + r;

    for (int t = 0; t < TT; t++) {
        const int src = t & 1, dst = src ^ 1;
        int acc1[2][2][4] = {};
        int acc2[2][2][4] = {};

        const int* __restrict__ xrow = g_xT + t * BB;
        const int tokA0 = xrow[gmA_base];
        const int tokB0 = xrow[gmA_base + 8];
        const int tokA1 = xrow[gmA_base + 16];
        const int tokB1 = xrow[gmA_base + 24];

        if (t > 0) {
            const uint8_t* __restrict__ Hsrc = g_Hq[src];
            CWAIT(my_bar, 16u * (unsigned)t);
            ISSUE_A(0);
            #pragma unroll
            for (int kb = 0; kb < 4; kb++) {
                CP_WAIT0();
                __syncthreads();
                if (kb < 3) ISSUE_A(kb + 1);
                compute_stage_s8(aB + (kb & 1) * 32768, bB, kb,
                                 warp_m, warp_n, lane, acc1, acc2);
            }
        }

        {
            uint8_t* __restrict__ hbase = g_Hq[dst];
            const int toks[2][2] = {{tokA0, tokB0}, {tokA1, tokB1}};
            #pragma unroll
            for (int mi = 0; mi < 2; mi++) {
                const int gmA = gmA_base + mi * 16;
                const int gmB = gmA + 8;
                const float* __restrict__ pA = g_P + (size_t)toks[mi][0] * UU;
                const float* __restrict__ pB = g_P + (size_t)toks[mi][1] * UU;
                uint8_t* __restrict__ dA = hbase + (size_t)gmA * HROW;
                uint8_t* __restrict__ dB = hbase + (size_t)gmB * HROW;
                #pragma unroll
                for (int ni = 0; ni < 2; ni++) {
                    const int gc = N0 + warp_n * 16 + ni * 8 + q * 2;
                    float2 pa = *(const float2*)(pA + gc);
                    float2 pb = *(const float2*)(pB + gc);
                    float h0 = fast_tanh((float)acc1[mi][ni][0] * f1 + (float)acc2[mi][ni][0] * f2 + pa.x);
                    float h1 = fast_tanh((float)acc1[mi][ni][1] * f1 + (float)acc2[mi][ni][1] * f2 + pa.y);
                    float h2 = fast_tanh((float)acc1[mi][ni][2] * f1 + (float)acc2[mi][ni][2] * f2 + pb.x);
                    float h3 = fast_tanh((float)acc1[mi][ni][3] * f1 + (float)acc2[mi][ni][3] * f2 + pb.y);
                    int a1i, a2i, b1i, b2i, c1i, c2i, d1i, d2i;
                    hquant(h0, a1i, a2i); hquant(h1, b1i, b2i);
                    hquant(h2, c1i, c2i); hquant(h3, d1i, d2i);
                    *(unsigned short*)(dA + gc) =
                        (unsigned short)((a1i & 0xFF) | ((b1i & 0xFF) << 8));
                    *(unsigned short*)(dA + 512 + gc) =
                        (unsigned short)((a2i & 0xFF) | ((b2i & 0xFF) << 8));
                    *(unsigned short*)(dB + gc) =
                        (unsigned short)((c1i & 0xFF) | ((d1i & 0xFF) << 8));
                    *(unsigned short*)(dB + 512 + gc) =
                        (unsigned short)((c2i & 0xFF) | ((d2i & 0xFF) << 8));
                }
            }
        }

        __syncthreads();
        if (tid == 0)
            asm volatile("red.release.gpu.global.add.u32 [%0], 1;" :: "l"(my_bar) : "memory");
    }
    #undef ISSUE_A

    if (n_tile == 0) {
        CWAIT(my_bar, 16u * TT);
        const uint8_t* __restrict__ hb = g_Hq[0];
        const float bo = bout[0];
        #pragma unroll 4
        for (int rr = 0; rr < 16; rr++) {
            const int gm = M0 + wid * 16 + rr;
            const uint8_t* row = hb + (size_t)gm * HROW;
            float s = 0.f;
            #pragma unroll
            for (int k = lane; k < UU; k += 32) {
                float hv = (float)((int8_t)row[k]) * C_A1
                         + (float)((int8_t)row[512 + k]) * C_A2;
                s += hv * Wout[k];
            }
            #pragma unroll
            for (int o = 16; o; o >>= 1) s += __shfl_xor_sync(0xFFFFFFFFu, s, o);
            if (lane == 0) out[gm] = 1.f / (1.f + expf(-(s + bo)));
        }
    }
}

// ================= launcher =================
extern "C" void kernel_launch(void* const* d_in, const int* in_sizes, int n_in,
                              void* d_out, int out_size)
{
    (void)in_sizes; (void)n_in; (void)out_size;
    const int*   x    = (const int*)  d_in[0];
    const float* emb  = (const float*)d_in[1];
    // Wx0/Wh0/b0 (d_in[2..4]) are dead code in the reference.
    const float* Wx1  = (const float*)d_in[5];
    const float* Wh1  = (const float*)d_in[6];
    const float* b1   = (const float*)d_in[7];
    const float* Wout = (const float*)d_in[8];
    const float* bout = (const float*)d_in[9];
    float* out = (float*)d_out;

    cudaFuncSetAttribute(rnn_kernel, cudaFuncAttributeMaxDynamicSharedMemorySize, SM_TOT);
    cudaFuncSetAttribute(p_imma_kernel, cudaFuncAttributeMaxDynamicSharedMemorySize, PSM_TOT);

    reset_kernel<<<1, 32>>>();
    max_kernel<<<(VV * EE + 1023) / 1024, 256>>>(emb, Wh1, Wx1);
    quant_kernel<<<VV * 128 / 256, 256>>>(emb, Wh1, Wx1, x);
    p_imma_kernel<<<dim3(UU / NT, VPAD / MT), 256, PSM_TOT>>>(b1);
    rnn_kernel<<<NCTA, 256, SM_TOT>>>(Wout, bout, out);
}